// round 8
// baseline (speedup 1.0000x reference)
#include <cuda_runtime.h>
#include <cuda_bf16.h>
#include <cstdint>

#define NNODES 50000
#define NEDGES 800000
#define DIN    256
#define DH     128
#define NLAB   1000
#define NSCANB 196   // ceil(50000/256)

// ---------------- scratch (static device allocations; no cudaMalloc) --------
__device__ float g_ha[NNODES * DH];
__device__ float g_hb[NNODES * DH];
__device__ float g_res[NNODES * DH];
__device__ __nv_bfloat16 g_aggh[NNODES * DH];
__device__ __nv_bfloat16 g_aggl[NNODES * DH];
__device__ __nv_bfloat16 g_hah[NNODES * DH];
__device__ __nv_bfloat16 g_hal[NNODES * DH];
__device__ __nv_bfloat16 g_wih[DIN * DH],  g_wil[DIN * DH];
__device__ __nv_bfloat16 g_w1h[DH * DH],   g_w1l[DH * DH];
__device__ __nv_bfloat16 g_w2h[DH * DH],   g_w2l[DH * DH];
__device__ __nv_bfloat16 g_woh[DH * NLAB], g_wol[DH * NLAB];
__device__ int   g_cnt[NNODES];          // zero-init; left zero after each call
__device__ int   g_rowptr[NNODES + 1];
__device__ int   g_cursor[NNODES];
__device__ int   g_bsum[NSCANB];
__device__ int   g_csrc[NEDGES];
__device__ float g_csw[NEDGES];
__device__ float g_cpw[NEDGES];

// ---------------- helpers ----------------------------------------------------
__device__ __forceinline__ uint32_t smem_u32(const void* p) {
    uint32_t a;
    asm("{ .reg .u64 t; cvta.to.shared.u64 t, %1; cvt.u32.u64 %0, t; }" : "=r"(a) : "l"(p));
    return a;
}
__device__ __forceinline__ uint32_t pack_bf2(float e0, float e1) {
    // low half = bf16(e0), high half = bf16(e1)
    uint32_t r;
    asm("cvt.rn.satfinite.bf16x2.f32 %0, %1, %2;" : "=r"(r) : "f"(e1), "f"(e0));
    return r;
}

#define LDSM4(r, addr)                                                          \
    asm volatile("ldmatrix.sync.aligned.m8n8.x4.shared.b16 {%0,%1,%2,%3}, [%4];"\
        : "=r"((r)[0]), "=r"((r)[1]), "=r"((r)[2]), "=r"((r)[3]) : "r"(addr))
#define LDSM4T(r, addr)                                                         \
    asm volatile("ldmatrix.sync.aligned.m8n8.x4.trans.shared.b16 {%0,%1,%2,%3}, [%4];"\
        : "=r"((r)[0]), "=r"((r)[1]), "=r"((r)[2]), "=r"((r)[3]) : "r"(addr))
#define MMA16816(d, a, b)                                                       \
    asm volatile("mma.sync.aligned.m16n8k16.row.col.f32.bf16.bf16.f32 "         \
        "{%0,%1,%2,%3}, {%4,%5,%6,%7}, {%8,%9}, {%0,%1,%2,%3};"                 \
        : "+f"((d)[0]), "+f"((d)[1]), "+f"((d)[2]), "+f"((d)[3])                \
        : "r"((a)[0]), "r"((a)[1]), "r"((a)[2]), "r"((a)[3]),                   \
          "r"((b)[0]), "r"((b)[1]))

// ---------------- weight pre-split ------------------------------------------
__global__ void split_kernel(const float* __restrict__ in, __nv_bfloat16* __restrict__ hi,
                             __nv_bfloat16* __restrict__ lo, int L) {
    int i = blockIdx.x * blockDim.x + threadIdx.x;
    if (i < L) {
        float v = in[i];
        __nv_bfloat16 h = __float2bfloat16(v);
        hi[i] = h;
        lo[i] = __float2bfloat16(v - __bfloat162float(h));
    }
}

// ---------------- CSR build -------------------------------------------------
__global__ void hist_kernel(const int* __restrict__ dst, int E) {
    int i = blockIdx.x * blockDim.x + threadIdx.x;
    if (i < E) atomicAdd(&g_cnt[dst[i]], 1);
}
__global__ void scanA_kernel() {
    __shared__ int wsum[8];
    int i = blockIdx.x * 256 + threadIdx.x;
    int lane = threadIdx.x & 31, wid = threadIdx.x >> 5;
    int v = (i < NNODES) ? g_cnt[i] : 0;
    #pragma unroll
    for (int off = 16; off > 0; off >>= 1) v += __shfl_down_sync(0xFFFFFFFFu, v, off);
    if (lane == 0) wsum[wid] = v;
    __syncthreads();
    if (threadIdx.x == 0) {
        int s = 0;
        #pragma unroll
        for (int w = 0; w < 8; w++) s += wsum[w];
        g_bsum[blockIdx.x] = s;
    }
}
__global__ void scanB_kernel() {
    __shared__ int wsc[8];
    int t = threadIdx.x;
    int lane = t & 31, wid = t >> 5;
    int v = (t < NSCANB) ? g_bsum[t] : 0;
    int incl = v;
    #pragma unroll
    for (int off = 1; off < 32; off <<= 1) {
        int u = __shfl_up_sync(0xFFFFFFFFu, incl, off);
        if (lane >= off) incl += u;
    }
    if (lane == 31) wsc[wid] = incl;
    __syncthreads();
    if (wid == 0) {
        int ws = (lane < 8) ? wsc[lane] : 0;
        #pragma unroll
        for (int off = 1; off < 8; off <<= 1) {
            int u = __shfl_up_sync(0xFFFFFFFFu, ws, off);
            if (lane >= off) ws += u;
        }
        if (lane < 8) wsc[lane] = ws;
    }
    __syncthreads();
    int excl = incl - v + (wid ? wsc[wid - 1] : 0);
    if (t < NSCANB) g_bsum[t] = excl;
    if (t == 255) g_rowptr[NNODES] = excl + v;
}
__global__ void scanC_kernel() {
    __shared__ int wsc[8];
    int i = blockIdx.x * 256 + threadIdx.x;
    int t = threadIdx.x, lane = t & 31, wid = t >> 5;
    int v = (i < NNODES) ? g_cnt[i] : 0;
    int incl = v;
    #pragma unroll
    for (int off = 1; off < 32; off <<= 1) {
        int u = __shfl_up_sync(0xFFFFFFFFu, incl, off);
        if (lane >= off) incl += u;
    }
    if (lane == 31) wsc[wid] = incl;
    __syncthreads();
    if (wid == 0) {
        int ws = (lane < 8) ? wsc[lane] : 0;
        #pragma unroll
        for (int off = 1; off < 8; off <<= 1) {
            int u = __shfl_up_sync(0xFFFFFFFFu, ws, off);
            if (lane >= off) ws += u;
        }
        if (lane < 8) wsc[lane] = ws;
    }
    __syncthreads();
    int excl = incl - v + (wid ? wsc[wid - 1] : 0) + g_bsum[blockIdx.x];
    if (i < NNODES) {
        g_rowptr[i] = excl;
        g_cursor[i] = excl;
        g_cnt[i] = 0;
    }
}
__global__ void scatter_kernel(const int* __restrict__ src, const int* __restrict__ dst,
                               const float* __restrict__ sw, const float* __restrict__ pw,
                               int E) {
    int i = blockIdx.x * blockDim.x + threadIdx.x;
    if (i < E) {
        int d = dst[i];
        int pos = atomicAdd(&g_cursor[d], 1);
        g_csrc[pos] = src[i];
        g_csw[pos]  = sw[i];
        g_cpw[pos]  = pw[i];
    }
}

// ---------------- aggregation: warp per dst; emits res fp32 + agg hi/lo -----
__global__ void aggregate_kernel(const float* __restrict__ h) {
    int warp = (blockIdx.x * blockDim.x + threadIdx.x) >> 5;
    int lane = threadIdx.x & 31;
    if (warp >= NNODES) return;
    int beg = g_rowptr[warp];
    int end = g_rowptr[warp + 1];
    float4 as = make_float4(0.f, 0.f, 0.f, 0.f);
    float4 ap = make_float4(0.f, 0.f, 0.f, 0.f);
    int e = beg;
    for (; e + 1 < end; e += 2) {
        int   s0 = g_csrc[e], s1 = g_csrc[e + 1];
        float sw0 = g_csw[e], pw0 = g_cpw[e];
        float sw1 = g_csw[e + 1], pw1 = g_cpw[e + 1];
        float4 h0 = *reinterpret_cast<const float4*>(&h[(size_t)s0 * DH + lane * 4]);
        float4 h1 = *reinterpret_cast<const float4*>(&h[(size_t)s1 * DH + lane * 4]);
        as.x += sw0 * h0.x; as.y += sw0 * h0.y; as.z += sw0 * h0.z; as.w += sw0 * h0.w;
        ap.x += pw0 * h0.x; ap.y += pw0 * h0.y; ap.z += pw0 * h0.z; ap.w += pw0 * h0.w;
        as.x += sw1 * h1.x; as.y += sw1 * h1.y; as.z += sw1 * h1.z; as.w += sw1 * h1.w;
        ap.x += pw1 * h1.x; ap.y += pw1 * h1.y; ap.z += pw1 * h1.z; ap.w += pw1 * h1.w;
    }
    if (e < end) {
        int   s0 = g_csrc[e];
        float sw0 = g_csw[e], pw0 = g_cpw[e];
        float4 h0 = *reinterpret_cast<const float4*>(&h[(size_t)s0 * DH + lane * 4]);
        as.x += sw0 * h0.x; as.y += sw0 * h0.y; as.z += sw0 * h0.z; as.w += sw0 * h0.w;
        ap.x += pw0 * h0.x; ap.y += pw0 * h0.y; ap.z += pw0 * h0.z; ap.w += pw0 * h0.w;
    }
    *reinterpret_cast<float4*>(&g_res[(size_t)warp * DH + lane * 4]) = as;
    // split agg to bf16 hi/lo planes
    uint32_t h01 = pack_bf2(ap.x, ap.y);
    uint32_t h23 = pack_bf2(ap.z, ap.w);
    float hx = __uint_as_float(h01 << 16);
    float hy = __uint_as_float(h01 & 0xFFFF0000u);
    float hz = __uint_as_float(h23 << 16);
    float hw = __uint_as_float(h23 & 0xFFFF0000u);
    uint32_t l01 = pack_bf2(ap.x - hx, ap.y - hy);
    uint32_t l23 = pack_bf2(ap.z - hz, ap.w - hw);
    size_t idx = (size_t)warp * DH + lane * 4;
    *reinterpret_cast<uint2*>(&g_aggh[idx]) = make_uint2(h01, h23);
    *reinterpret_cast<uint2*>(&g_aggl[idx]) = make_uint2(l01, l23);
}

// ---------------- bf16-split GEMM on HMMA, register-prefetch pipelined ------
// C = op(A @ B + bias) [+Res]; A either fp32 (AMODE 0, converted in-loop) or
// pre-split bf16 planes (AMODE 1). B always pre-split planes.
// EPI: 0 = relu->fp32, 1 = relu+res->fp32, 2 = relu+res->hi/lo planes, 3 = plain fp32.
#define SA_STRIDE 80
#define SB_STRIDE 272
#define OFF_A_HI 0
#define OFF_A_LO 10240
#define OFF_B_HI 20480
#define OFF_B_LO 29184
#define OFF_BIAS 37888
#define SM_TOTAL 38400

template<int AMODE, int EPI>
__global__ __launch_bounds__(256)
void mma_gemm(const float* __restrict__ A,
              const __nv_bfloat16* __restrict__ Ahi, const __nv_bfloat16* __restrict__ Alo,
              const __nv_bfloat16* __restrict__ Bhi, const __nv_bfloat16* __restrict__ Blo,
              const float* __restrict__ bias, const float* __restrict__ Res,
              float* __restrict__ Cf,
              __nv_bfloat16* __restrict__ Chi, __nv_bfloat16* __restrict__ Clo,
              int M, int K, int Nc) {
    __shared__ __align__(16) char smem[SM_TOTAL];
    const uint32_t sb = smem_u32(smem);
    const int tid  = threadIdx.x;
    const int wid  = tid >> 5;
    const int lane = tid & 31;
    const int rowBase = blockIdx.x * 128;
    const int colBase = blockIdx.y * 128;
    const int wm = (wid >> 1) * 32;
    const int wn = (wid & 1) * 64;
    float* bias_s = reinterpret_cast<float*>(smem + OFF_BIAS);

    if (tid < 128) {
        int gc = colBase + tid;
        bias_s[tid] = (gc < Nc) ? bias[gc] : 0.f;
    }

    // staging registers
    float4 paf[4];      // AMODE 0
    uint4  pa4[4];      // AMODE 1 (2 hi granule + 2 lo granule sets x2)
    uint4  pb4[4];

    auto loadA = [&](int k0) {
        if (AMODE == 0) {
            #pragma unroll
            for (int u = 0; u < 4; u++) {
                int it = tid + u * 256;           // r=it>>3, kq=(it&7)*4
                int r  = it >> 3;
                int kq = (it & 7) << 2;
                int gr = rowBase + r;
                paf[u] = (gr < M) ? *reinterpret_cast<const float4*>(&A[(size_t)gr * K + k0 + kq])
                                  : make_float4(0.f, 0.f, 0.f, 0.f);
            }
        } else {
            #pragma unroll
            for (int u = 0; u < 4; u++) {
                int g = tid + u * 256;            // 1024 granules: [0,512) hi, [512,1024) lo
                int idx = g & 511;
                int r   = idx >> 2;
                int c16 = idx & 3;
                int gr  = rowBase + r;
                const __nv_bfloat16* plane = (g < 512) ? Ahi : Alo;
                pa4[u] = (gr < M)
                    ? *reinterpret_cast<const uint4*>(&plane[(size_t)gr * K + k0 + c16 * 8])
                    : make_uint4(0u, 0u, 0u, 0u);
            }
        }
    };
    auto loadB = [&](int k0) {
        #pragma unroll
        for (int u = 0; u < 4; u++) {
            int g = tid + u * 256;                // 1024 granules: [0,512) hi, [512,1024) lo
            int idx = g & 511;
            int kr  = idx >> 4;
            int c16 = idx & 15;
            int gc  = colBase + c16 * 8;
            const __nv_bfloat16* plane = (g < 512) ? Bhi : Blo;
            pb4[u] = (gc + 8 <= Nc)
                ? *reinterpret_cast<const uint4*>(&plane[(size_t)(k0 + kr) * Nc + gc])
                : make_uint4(0u, 0u, 0u, 0u);
        }
    };
    auto storeAB = [&]() {
        if (AMODE == 0) {
            #pragma unroll
            for (int u = 0; u < 4; u++) {
                int it = tid + u * 256;
                int r  = it >> 3;
                int kq = (it & 7) << 2;
                float4 v = paf[u];
                uint32_t hp01 = pack_bf2(v.x, v.y);
                uint32_t hp23 = pack_bf2(v.z, v.w);
                float hx = __uint_as_float(hp01 << 16);
                float hy = __uint_as_float(hp01 & 0xFFFF0000u);
                float hz = __uint_as_float(hp23 << 16);
                float hw = __uint_as_float(hp23 & 0xFFFF0000u);
                uint32_t lp01 = pack_bf2(v.x - hx, v.y - hy);
                uint32_t lp23 = pack_bf2(v.z - hz, v.w - hw);
                int ad = r * SA_STRIDE + kq * 2;
                *reinterpret_cast<uint2*>(smem + OFF_A_HI + ad) = make_uint2(hp01, hp23);
                *reinterpret_cast<uint2*>(smem + OFF_A_LO + ad) = make_uint2(lp01, lp23);
            }
        } else {
            #pragma unroll
            for (int u = 0; u < 4; u++) {
                int g = tid + u * 256;
                int idx = g & 511;
                int r   = idx >> 2;
                int c16 = idx & 3;
                int off = (g < 512) ? OFF_A_HI : OFF_A_LO;
                *reinterpret_cast<uint4*>(smem + off + r * SA_STRIDE + c16 * 16) = pa4[u];
            }
        }
        #pragma unroll
        for (int u = 0; u < 4; u++) {
            int g = tid + u * 256;
            int idx = g & 511;
            int kr  = idx >> 4;
            int c16 = idx & 15;
            int off = (g < 512) ? OFF_B_HI : OFF_B_LO;
            *reinterpret_cast<uint4*>(smem + off + kr * SB_STRIDE + c16 * 16) = pb4[u];
        }
    };

    float acc[2][8][4];
    #pragma unroll
    for (int mt = 0; mt < 2; mt++)
        #pragma unroll
        for (int nt = 0; nt < 8; nt++)
            #pragma unroll
            for (int q = 0; q < 4; q++) acc[mt][nt][q] = 0.f;

    const int nch = K >> 5;
    loadA(0); loadB(0);

    for (int ch = 0; ch < nch; ch++) {
        storeAB();
        __syncthreads();
        if (ch + 1 < nch) { loadA((ch + 1) << 5); loadB((ch + 1) << 5); }

        #pragma unroll
        for (int kk = 0; kk < 32; kk += 16) {
            uint32_t ahi[2][4], alo[2][4];
            #pragma unroll
            for (int mt = 0; mt < 2; mt++) {
                int row = wm + mt * 16 + (lane & 15);
                int col = kk + ((lane >> 4) << 3);
                uint32_t aadr = sb + OFF_A_HI + row * SA_STRIDE + col * 2;
                LDSM4(ahi[mt], aadr);
                LDSM4(alo[mt], aadr + (OFF_A_LO - OFF_A_HI));
            }
            #pragma unroll
            for (int g = 0; g < 4; g++) {
                int krow = kk + ((lane >> 3) & 1) * 8 + (lane & 7);
                int ncol = wn + g * 16 + ((lane >> 4) << 3);
                uint32_t badr = sb + OFF_B_HI + krow * SB_STRIDE + ncol * 2;
                uint32_t bh[4], bl[4];
                LDSM4T(bh, badr);
                LDSM4T(bl, badr + (OFF_B_LO - OFF_B_HI));
                #pragma unroll
                for (int half = 0; half < 2; half++) {
                    int nt = g * 2 + half;
                    #pragma unroll
                    for (int mt = 0; mt < 2; mt++) {
                        MMA16816(acc[mt][nt], ahi[mt], bh + 2 * half);
                        MMA16816(acc[mt][nt], ahi[mt], bl + 2 * half);
                        MMA16816(acc[mt][nt], alo[mt], bh + 2 * half);
                    }
                }
            }
        }
        __syncthreads();
    }

    // ---- epilogue ----
    const int g4 = lane >> 2;
    const int t4 = lane & 3;
    #pragma unroll
    for (int mt = 0; mt < 2; mt++) {
        #pragma unroll
        for (int half = 0; half < 2; half++) {
            int gr = rowBase + wm + mt * 16 + g4 + half * 8;
            if (gr >= M) continue;
            #pragma unroll
            for (int nt = 0; nt < 8; nt++) {
                int cl = wn + nt * 8 + t4 * 2;
                int gc = colBase + cl;
                float v0 = acc[mt][nt][half * 2]     + bias_s[cl];
                float v1 = acc[mt][nt][half * 2 + 1] + bias_s[cl + 1];
                if (EPI == 0 || EPI == 1 || EPI == 2) { v0 = fmaxf(v0, 0.f); v1 = fmaxf(v1, 0.f); }
                if (EPI == 1 || EPI == 2) {
                    float2 rr = *reinterpret_cast<const float2*>(&Res[(size_t)gr * Nc + gc]);
                    v0 += rr.x; v1 += rr.y;
                }
                if (EPI == 2) {
                    uint32_t hp = pack_bf2(v0, v1);
                    float h0 = __uint_as_float(hp << 16);
                    float h1 = __uint_as_float(hp & 0xFFFF0000u);
                    uint32_t lp = pack_bf2(v0 - h0, v1 - h1);
                    size_t idx = (size_t)gr * Nc + gc;
                    *reinterpret_cast<uint32_t*>(&Chi[idx]) = hp;
                    *reinterpret_cast<uint32_t*>(&Clo[idx]) = lp;
                } else {
                    if (gc + 1 < Nc) {
                        *reinterpret_cast<float2*>(&Cf[(size_t)gr * Nc + gc]) = make_float2(v0, v1);
                    } else if (gc < Nc) {
                        Cf[(size_t)gr * Nc + gc] = v0;
                    }
                }
            }
        }
    }
}

// ---------------- launch ----------------------------------------------------
extern "C" void kernel_launch(void* const* d_in, const int* in_sizes, int n_in,
                              void* d_out, int out_size) {
    const float* x      = (const float*)d_in[0];
    const int*   src    = (const int*)  d_in[1];
    const int*   dst    = (const int*)  d_in[2];
    const float* self_w = (const float*)d_in[3];
    const float* ppi_w  = (const float*)d_in[4];
    const float* W_in   = (const float*)d_in[5];
    const float* b_in   = (const float*)d_in[6];
    const float* W1     = (const float*)d_in[7];
    const float* b1     = (const float*)d_in[8];
    const float* W2     = (const float*)d_in[9];
    const float* b2     = (const float*)d_in[10];
    const float* W_out  = (const float*)d_in[11];
    const float* b_out  = (const float*)d_in[12];
    float* out = (float*)d_out;
    const int E = in_sizes[1];

    float *ha, *hb, *res;
    __nv_bfloat16 *aggh, *aggl, *hah, *hal;
    __nv_bfloat16 *wih, *wil, *w1h, *w1l, *w2h, *w2l, *woh, *wol;
    cudaGetSymbolAddress((void**)&ha,   g_ha);
    cudaGetSymbolAddress((void**)&hb,   g_hb);
    cudaGetSymbolAddress((void**)&res,  g_res);
    cudaGetSymbolAddress((void**)&aggh, g_aggh);
    cudaGetSymbolAddress((void**)&aggl, g_aggl);
    cudaGetSymbolAddress((void**)&hah,  g_hah);
    cudaGetSymbolAddress((void**)&hal,  g_hal);
    cudaGetSymbolAddress((void**)&wih,  g_wih);
    cudaGetSymbolAddress((void**)&wil,  g_wil);
    cudaGetSymbolAddress((void**)&w1h,  g_w1h);
    cudaGetSymbolAddress((void**)&w1l,  g_w1l);
    cudaGetSymbolAddress((void**)&w2h,  g_w2h);
    cudaGetSymbolAddress((void**)&w2l,  g_w2l);
    cudaGetSymbolAddress((void**)&woh,  g_woh);
    cudaGetSymbolAddress((void**)&wol,  g_wol);

    const dim3 blk(256);
    const dim3 g_h((NNODES + 127) / 128, 1);
    const dim3 g_o((NNODES + 127) / 128, (NLAB + 127) / 128);
    const int agg_blocks = (NNODES * 32 + 255) / 256;

    // pre-split all weights into bf16 hi/lo planes
    split_kernel<<<(DIN * DH + 255) / 256, 256>>>(W_in,  wih, wil, DIN * DH);
    split_kernel<<<(DH * DH + 255) / 256, 256>>>(W1,    w1h, w1l, DH * DH);
    split_kernel<<<(DH * DH + 255) / 256, 256>>>(W2,    w2h, w2l, DH * DH);
    split_kernel<<<(DH * NLAB + 255) / 256, 256>>>(W_out, woh, wol, DH * NLAB);

    // h = relu(x @ W_in + b_in)
    mma_gemm<0, 0><<<g_h, blk>>>(x, nullptr, nullptr, wih, wil, b_in, nullptr,
                                 ha, nullptr, nullptr, NNODES, DIN, DH);

    // CSR by dst (g_cnt zero on entry, re-zeroed in scanC)
    hist_kernel<<<(E + 255) / 256, 256>>>(dst, E);
    scanA_kernel<<<NSCANB, 256>>>();
    scanB_kernel<<<1, 256>>>();
    scanC_kernel<<<NSCANB, 256>>>();
    scatter_kernel<<<(E + 255) / 256, 256>>>(src, dst, self_w, ppi_w, E);

    // layer 1: agg planes + res from ha; hb = relu(agg@W1+b1)+res
    aggregate_kernel<<<agg_blocks, blk>>>(ha);
    mma_gemm<1, 1><<<g_h, blk>>>(nullptr, aggh, aggl, w1h, w1l, b1, res,
                                 hb, nullptr, nullptr, NNODES, DH, DH);
    // layer 2: ha2 = relu(agg@W2+b2)+res, emitted as hi/lo planes
    aggregate_kernel<<<agg_blocks, blk>>>(hb);
    mma_gemm<1, 2><<<g_h, blk>>>(nullptr, aggh, aggl, w2h, w2l, b2, res,
                                 nullptr, hah, hal, NNODES, DH, DH);
    // out = ha2 @ W_out + b_out
    mma_gemm<1, 3><<<g_o, blk>>>(nullptr, hah, hal, woh, wol, b_out, nullptr,
                                 out, nullptr, nullptr, NNODES, DH, NLAB);
}

// round 10
// speedup vs baseline: 1.5411x; 1.5411x over previous
#include <cuda_runtime.h>
#include <cuda_bf16.h>
#include <cstdint>

#define NNODES 50000
#define NEDGES 800000
#define DIN    256
#define DH     128
#define NLAB   1000
#define NSCANB 196   // ceil(50000/256)

// ---------------- scratch (static device allocations; no cudaMalloc) --------
__device__ float g_ha[NNODES * DH];
__device__ float g_hb[NNODES * DH];
__device__ float g_agg[NNODES * DH];
__device__ float g_res[NNODES * DH];
__device__ int   g_cnt[NNODES];          // zero-init; left zero after each call
__device__ int   g_rowptr[NNODES + 1];
__device__ int   g_cursor[NNODES];
__device__ int   g_bsum[NSCANB];
__device__ int   g_csrc[NEDGES];
__device__ float g_csw[NEDGES];
__device__ float g_cpw[NEDGES];

// ---------------- helpers ----------------------------------------------------
__device__ __forceinline__ uint32_t smem_u32(const void* p) {
    uint32_t a;
    asm("{ .reg .u64 t; cvta.to.shared.u64 t, %1; cvt.u32.u64 %0, t; }" : "=r"(a) : "l"(p));
    return a;
}
__device__ __forceinline__ uint32_t pack_bf2(float e0, float e1) {
    // low half = bf16(e0), high half = bf16(e1)
    uint32_t r;
    asm("cvt.rn.satfinite.bf16x2.f32 %0, %1, %2;" : "=r"(r) : "f"(e1), "f"(e0));
    return r;
}

#define LDSM4(r, addr)                                                          \
    asm volatile("ldmatrix.sync.aligned.m8n8.x4.shared.b16 {%0,%1,%2,%3}, [%4];"\
        : "=r"((r)[0]), "=r"((r)[1]), "=r"((r)[2]), "=r"((r)[3]) : "r"(addr))
#define LDSM4T(r, addr)                                                         \
    asm volatile("ldmatrix.sync.aligned.m8n8.x4.trans.shared.b16 {%0,%1,%2,%3}, [%4];"\
        : "=r"((r)[0]), "=r"((r)[1]), "=r"((r)[2]), "=r"((r)[3]) : "r"(addr))
#define MMA16816(d, a, b)                                                       \
    asm volatile("mma.sync.aligned.m16n8k16.row.col.f32.bf16.bf16.f32 "         \
        "{%0,%1,%2,%3}, {%4,%5,%6,%7}, {%8,%9}, {%0,%1,%2,%3};"                 \
        : "+f"((d)[0]), "+f"((d)[1]), "+f"((d)[2]), "+f"((d)[3])                \
        : "r"((a)[0]), "r"((a)[1]), "r"((a)[2]), "r"((a)[3]),                   \
          "r"((b)[0]), "r"((b)[1]))

// ---------------- CSR build -------------------------------------------------
__global__ void hist_kernel(const int* __restrict__ dst, int E) {
    int i = blockIdx.x * blockDim.x + threadIdx.x;
    if (i < E) atomicAdd(&g_cnt[dst[i]], 1);
}
__global__ void scanA_kernel() {
    __shared__ int wsum[8];
    int i = blockIdx.x * 256 + threadIdx.x;
    int lane = threadIdx.x & 31, wid = threadIdx.x >> 5;
    int v = (i < NNODES) ? g_cnt[i] : 0;
    #pragma unroll
    for (int off = 16; off > 0; off >>= 1) v += __shfl_down_sync(0xFFFFFFFFu, v, off);
    if (lane == 0) wsum[wid] = v;
    __syncthreads();
    if (threadIdx.x == 0) {
        int s = 0;
        #pragma unroll
        for (int w = 0; w < 8; w++) s += wsum[w];
        g_bsum[blockIdx.x] = s;
    }
}
__global__ void scanB_kernel() {
    __shared__ int wsc[8];
    int t = threadIdx.x;
    int lane = t & 31, wid = t >> 5;
    int v = (t < NSCANB) ? g_bsum[t] : 0;
    int incl = v;
    #pragma unroll
    for (int off = 1; off < 32; off <<= 1) {
        int u = __shfl_up_sync(0xFFFFFFFFu, incl, off);
        if (lane >= off) incl += u;
    }
    if (lane == 31) wsc[wid] = incl;
    __syncthreads();
    if (wid == 0) {
        int ws = (lane < 8) ? wsc[lane] : 0;
        #pragma unroll
        for (int off = 1; off < 8; off <<= 1) {
            int u = __shfl_up_sync(0xFFFFFFFFu, ws, off);
            if (lane >= off) ws += u;
        }
        if (lane < 8) wsc[lane] = ws;
    }
    __syncthreads();
    int excl = incl - v + (wid ? wsc[wid - 1] : 0);
    if (t < NSCANB) g_bsum[t] = excl;
    if (t == 255) g_rowptr[NNODES] = excl + v;
}
__global__ void scanC_kernel() {
    __shared__ int wsc[8];
    int i = blockIdx.x * 256 + threadIdx.x;
    int t = threadIdx.x, lane = t & 31, wid = t >> 5;
    int v = (i < NNODES) ? g_cnt[i] : 0;
    int incl = v;
    #pragma unroll
    for (int off = 1; off < 32; off <<= 1) {
        int u = __shfl_up_sync(0xFFFFFFFFu, incl, off);
        if (lane >= off) incl += u;
    }
    if (lane == 31) wsc[wid] = incl;
    __syncthreads();
    if (wid == 0) {
        int ws = (lane < 8) ? wsc[lane] : 0;
        #pragma unroll
        for (int off = 1; off < 8; off <<= 1) {
            int u = __shfl_up_sync(0xFFFFFFFFu, ws, off);
            if (lane >= off) ws += u;
        }
        if (lane < 8) wsc[lane] = ws;
    }
    __syncthreads();
    int excl = incl - v + (wid ? wsc[wid - 1] : 0) + g_bsum[blockIdx.x];
    if (i < NNODES) {
        g_rowptr[i] = excl;
        g_cursor[i] = excl;
        g_cnt[i] = 0;
    }
}
__global__ void scatter_kernel(const int* __restrict__ src, const int* __restrict__ dst,
                               const float* __restrict__ sw, const float* __restrict__ pw,
                               int E) {
    int i = blockIdx.x * blockDim.x + threadIdx.x;
    if (i < E) {
        int d = dst[i];
        int pos = atomicAdd(&g_cursor[d], 1);
        g_csrc[pos] = src[i];
        g_csw[pos]  = sw[i];
        g_cpw[pos]  = pw[i];
    }
}

// ---------------- aggregation: warp per dst node ----------------------------
__global__ void aggregate_kernel(const float* __restrict__ h) {
    int warp = (blockIdx.x * blockDim.x + threadIdx.x) >> 5;
    int lane = threadIdx.x & 31;
    if (warp >= NNODES) return;
    int beg = g_rowptr[warp];
    int end = g_rowptr[warp + 1];
    float4 as = make_float4(0.f, 0.f, 0.f, 0.f);
    float4 ap = make_float4(0.f, 0.f, 0.f, 0.f);
    int e = beg;
    for (; e + 1 < end; e += 2) {
        int   s0 = g_csrc[e], s1 = g_csrc[e + 1];
        float sw0 = g_csw[e], pw0 = g_cpw[e];
        float sw1 = g_csw[e + 1], pw1 = g_cpw[e + 1];
        float4 h0 = *reinterpret_cast<const float4*>(&h[(size_t)s0 * DH + lane * 4]);
        float4 h1 = *reinterpret_cast<const float4*>(&h[(size_t)s1 * DH + lane * 4]);
        as.x += sw0 * h0.x; as.y += sw0 * h0.y; as.z += sw0 * h0.z; as.w += sw0 * h0.w;
        ap.x += pw0 * h0.x; ap.y += pw0 * h0.y; ap.z += pw0 * h0.z; ap.w += pw0 * h0.w;
        as.x += sw1 * h1.x; as.y += sw1 * h1.y; as.z += sw1 * h1.z; as.w += sw1 * h1.w;
        ap.x += pw1 * h1.x; ap.y += pw1 * h1.y; ap.z += pw1 * h1.z; ap.w += pw1 * h1.w;
    }
    if (e < end) {
        int   s0 = g_csrc[e];
        float sw0 = g_csw[e], pw0 = g_cpw[e];
        float4 h0 = *reinterpret_cast<const float4*>(&h[(size_t)s0 * DH + lane * 4]);
        as.x += sw0 * h0.x; as.y += sw0 * h0.y; as.z += sw0 * h0.z; as.w += sw0 * h0.w;
        ap.x += pw0 * h0.x; ap.y += pw0 * h0.y; ap.z += pw0 * h0.z; ap.w += pw0 * h0.w;
    }
    *reinterpret_cast<float4*>(&g_res[(size_t)warp * DH + lane * 4]) = as;
    *reinterpret_cast<float4*>(&g_agg[(size_t)warp * DH + lane * 4]) = ap;
}

// ---------------- bf16-split GEMM on HMMA ------------------------------------
// C[M,Nc] = op(A @ B + bias) [+Res], fp32 in/out.
// fp32 -> (hi,lo) bf16 in-loop; C = AhiBhi + AhiBlo + AloBhi with fp32 accum.
// Block 128x128, BK=32, 16 warps (warp tile 32M x 32N), m16n8k16 HMMA.
// 2-stage smem double buffer + register prefetch: global latency AND
// conversion/STS overlap with the HMMA burst; one sync per chunk.
#define SA_STRIDE 80
#define SB_STRIDE 272
#define OFF_A_HI 0
#define OFF_A_LO 10240
#define OFF_B_HI 20480
#define OFF_B_LO 29184
#define BUF_SZ   37888
#define OFF_BIAS 75776
#define SM_TOTAL 76288

template<bool RELU, bool ADDRES>
__global__ __launch_bounds__(512)
void mma_gemm(const float* __restrict__ A, const float* __restrict__ B,
              const float* __restrict__ bias, const float* __restrict__ Res,
              float* __restrict__ C, int M, int K, int Nc) {
    extern __shared__ __align__(16) char smem[];
    const uint32_t sb = smem_u32(smem);
    const int tid  = threadIdx.x;
    const int wid  = tid >> 5;
    const int lane = tid & 31;
    const int rowBase = blockIdx.x * 128;
    const int colBase = blockIdx.y * 128;
    const int wm = (wid >> 2) * 32;   // 0,32,64,96
    const int wn = (wid & 3) * 32;    // 0,32,64,96
    float* bias_s = reinterpret_cast<float*>(smem + OFF_BIAS);

    if (tid < 128) {
        int gc = colBase + tid;
        bias_s[tid] = (gc < Nc) ? bias[gc] : 0.f;
    }

    float4 pa[2], pb[2];

    auto loadA = [&](int k0) {
        #pragma unroll
        for (int u = 0; u < 2; u++) {
            int it = tid + u * 512;          // 1024 items: r=it>>3, kq=(it&7)*4
            int r  = it >> 3;
            int kq = (it & 7) << 2;
            int gr = rowBase + r;
            pa[u] = (gr < M) ? *reinterpret_cast<const float4*>(&A[(size_t)gr * K + k0 + kq])
                             : make_float4(0.f, 0.f, 0.f, 0.f);
        }
    };
    auto loadB = [&](int k0) {
        #pragma unroll
        for (int u = 0; u < 2; u++) {
            int it = tid + u * 512;          // 1024 items: kr=it>>5, nq=(it&31)*4
            int kr = it >> 5;
            int nq = (it & 31) << 2;
            int gc = colBase + nq;
            const float* Brow = &B[(size_t)(k0 + kr) * Nc];
            float4 v;
            if (gc + 3 < Nc) {
                v = *reinterpret_cast<const float4*>(&Brow[gc]);
            } else {
                v.x = (gc     < Nc) ? Brow[gc]     : 0.f;
                v.y = (gc + 1 < Nc) ? Brow[gc + 1] : 0.f;
                v.z = (gc + 2 < Nc) ? Brow[gc + 2] : 0.f;
                v.w = (gc + 3 < Nc) ? Brow[gc + 3] : 0.f;
            }
            pb[u] = v;
        }
    };
    auto storeAB = [&](int buf) {
        const int base = buf * BUF_SZ;
        #pragma unroll
        for (int u = 0; u < 2; u++) {
            int it = tid + u * 512;
            int r  = it >> 3;
            int kq = (it & 7) << 2;
            float4 v = pa[u];
            uint32_t hp01 = pack_bf2(v.x, v.y);
            uint32_t hp23 = pack_bf2(v.z, v.w);
            float hx = __uint_as_float(hp01 << 16);
            float hy = __uint_as_float(hp01 & 0xFFFF0000u);
            float hz = __uint_as_float(hp23 << 16);
            float hw = __uint_as_float(hp23 & 0xFFFF0000u);
            uint32_t lp01 = pack_bf2(v.x - hx, v.y - hy);
            uint32_t lp23 = pack_bf2(v.z - hz, v.w - hw);
            int ad = base + r * SA_STRIDE + kq * 2;
            *reinterpret_cast<uint2*>(smem + OFF_A_HI + ad) = make_uint2(hp01, hp23);
            *reinterpret_cast<uint2*>(smem + OFF_A_LO + ad) = make_uint2(lp01, lp23);
        }
        #pragma unroll
        for (int u = 0; u < 2; u++) {
            int it = tid + u * 512;
            int kr = it >> 5;
            int nq = (it & 31) << 2;
            float4 v = pb[u];
            uint32_t hp01 = pack_bf2(v.x, v.y);
            uint32_t hp23 = pack_bf2(v.z, v.w);
            float hx = __uint_as_float(hp01 << 16);
            float hy = __uint_as_float(hp01 & 0xFFFF0000u);
            float hz = __uint_as_float(hp23 << 16);
            float hw = __uint_as_float(hp23 & 0xFFFF0000u);
            uint32_t lp01 = pack_bf2(v.x - hx, v.y - hy);
            uint32_t lp23 = pack_bf2(v.z - hz, v.w - hw);
            int ad = base + kr * SB_STRIDE + nq * 2;
            *reinterpret_cast<uint2*>(smem + OFF_B_HI + ad) = make_uint2(hp01, hp23);
            *reinterpret_cast<uint2*>(smem + OFF_B_LO + ad) = make_uint2(lp01, lp23);
        }
    };

    float acc[2][4][4];
    #pragma unroll
    for (int mt = 0; mt < 2; mt++)
        #pragma unroll
        for (int nt = 0; nt < 4; nt++)
            #pragma unroll
            for (int q = 0; q < 4; q++) acc[mt][nt][q] = 0.f;

    const int nch = K >> 5;

    // prologue: fill buffer 0, prefetch chunk 1
    loadA(0); loadB(0);
    storeAB(0);
    if (nch > 1) { loadA(32); loadB(32); }
    __syncthreads();

    for (int ch = 0; ch < nch; ch++) {
        const int base = (ch & 1) * BUF_SZ;

        #pragma unroll
        for (int kk = 0; kk < 32; kk += 16) {
            uint32_t ahi[2][4], alo[2][4];
            #pragma unroll
            for (int mt = 0; mt < 2; mt++) {
                int row = wm + mt * 16 + (lane & 15);
                int col = kk + ((lane >> 4) << 3);
                uint32_t aadr = sb + OFF_A_HI + base + row * SA_STRIDE + col * 2;
                LDSM4(ahi[mt], aadr);
                LDSM4(alo[mt], aadr + (OFF_A_LO - OFF_A_HI));
            }
            #pragma unroll
            for (int g = 0; g < 2; g++) {
                int krow = kk + ((lane >> 3) & 1) * 8 + (lane & 7);
                int ncol = wn + g * 16 + ((lane >> 4) << 3);
                uint32_t badr = sb + OFF_B_HI + base + krow * SB_STRIDE + ncol * 2;
                uint32_t bh[4], bl[4];
                LDSM4T(bh, badr);
                LDSM4T(bl, badr + (OFF_B_LO - OFF_B_HI));
                #pragma unroll
                for (int half = 0; half < 2; half++) {
                    int nt = g * 2 + half;
                    #pragma unroll
                    for (int mt = 0; mt < 2; mt++) {
                        MMA16816(acc[mt][nt], ahi[mt], bh + 2 * half);
                        MMA16816(acc[mt][nt], ahi[mt], bl + 2 * half);
                        MMA16816(acc[mt][nt], alo[mt], bh + 2 * half);
                    }
                }
            }
        }

        // store next chunk into the other buffer, prefetch chunk after next
        if (ch + 1 < nch) {
            storeAB((ch + 1) & 1);
            if (ch + 2 < nch) { loadA((ch + 2) << 5); loadB((ch + 2) << 5); }
            __syncthreads();
        }
    }

    // ---- epilogue ----
    const int g4 = lane >> 2;
    const int t4 = lane & 3;
    #pragma unroll
    for (int mt = 0; mt < 2; mt++) {
        #pragma unroll
        for (int half = 0; half < 2; half++) {
            int gr = rowBase + wm + mt * 16 + g4 + half * 8;
            if (gr >= M) continue;
            #pragma unroll
            for (int nt = 0; nt < 4; nt++) {
                int cl = wn + nt * 8 + t4 * 2;
                int gc = colBase + cl;
                float v0 = acc[mt][nt][half * 2]     + bias_s[cl];
                float v1 = acc[mt][nt][half * 2 + 1] + bias_s[cl + 1];
                if (RELU) { v0 = fmaxf(v0, 0.f); v1 = fmaxf(v1, 0.f); }
                if (gc + 1 < Nc) {
                    if (ADDRES) {
                        float2 rr = *reinterpret_cast<const float2*>(&Res[(size_t)gr * Nc + gc]);
                        v0 += rr.x; v1 += rr.y;
                    }
                    *reinterpret_cast<float2*>(&C[(size_t)gr * Nc + gc]) = make_float2(v0, v1);
                } else if (gc < Nc) {
                    if (ADDRES) v0 += Res[(size_t)gr * Nc + gc];
                    C[(size_t)gr * Nc + gc] = v0;
                }
            }
        }
    }
}

// ---------------- launch ----------------------------------------------------
extern "C" void kernel_launch(void* const* d_in, const int* in_sizes, int n_in,
                              void* d_out, int out_size) {
    const float* x      = (const float*)d_in[0];
    const int*   src    = (const int*)  d_in[1];
    const int*   dst    = (const int*)  d_in[2];
    const float* self_w = (const float*)d_in[3];
    const float* ppi_w  = (const float*)d_in[4];
    const float* W_in   = (const float*)d_in[5];
    const float* b_in   = (const float*)d_in[6];
    const float* W1     = (const float*)d_in[7];
    const float* b1     = (const float*)d_in[8];
    const float* W2     = (const float*)d_in[9];
    const float* b2     = (const float*)d_in[10];
    const float* W_out  = (const float*)d_in[11];
    const float* b_out  = (const float*)d_in[12];
    float* out = (float*)d_out;
    const int E = in_sizes[1];

    float *ha, *hb, *agg, *res;
    cudaGetSymbolAddress((void**)&ha,  g_ha);
    cudaGetSymbolAddress((void**)&hb,  g_hb);
    cudaGetSymbolAddress((void**)&agg, g_agg);
    cudaGetSymbolAddress((void**)&res, g_res);

    cudaFuncSetAttribute(mma_gemm<true,  false>, cudaFuncAttributeMaxDynamicSharedMemorySize, SM_TOTAL);
    cudaFuncSetAttribute(mma_gemm<true,  true >, cudaFuncAttributeMaxDynamicSharedMemorySize, SM_TOTAL);
    cudaFuncSetAttribute(mma_gemm<false, false>, cudaFuncAttributeMaxDynamicSharedMemorySize, SM_TOTAL);

    const dim3 blk(512);
    const dim3 g_h((NNODES + 127) / 128, 1);
    const dim3 g_o((NNODES + 127) / 128, (NLAB + 127) / 128);
    const int agg_blocks = (NNODES * 32 + 255) / 256;

    // h = relu(x @ W_in + b_in)   (independent of CSR build; launch first)
    mma_gemm<true, false><<<g_h, blk, SM_TOTAL>>>(x, W_in, b_in, nullptr, ha, NNODES, DIN, DH);

    // CSR by dst (g_cnt zero on entry, re-zeroed in scanC)
    hist_kernel<<<(E + 255) / 256, 256>>>(dst, E);
    scanA_kernel<<<NSCANB, 256>>>();
    scanB_kernel<<<1, 256>>>();
    scanC_kernel<<<NSCANB, 256>>>();
    scatter_kernel<<<(E + 255) / 256, 256>>>(src, dst, self_w, ppi_w, E);

    // layer 1
    aggregate_kernel<<<agg_blocks, 256>>>(ha);
    mma_gemm<true, true><<<g_h, blk, SM_TOTAL>>>(agg, W1, b1, res, hb, NNODES, DH, DH);
    // layer 2
    aggregate_kernel<<<agg_blocks, 256>>>(hb);
    mma_gemm<true, true><<<g_h, blk, SM_TOTAL>>>(agg, W2, b2, res, ha, NNODES, DH, DH);
    // out = h @ W_out + b_out
    mma_gemm<false, false><<<g_o, blk, SM_TOTAL>>>(ha, W_out, b_out, nullptr, out, NNODES, DH, NLAB);
}

// round 11
// speedup vs baseline: 1.5834x; 1.0275x over previous
#include <cuda_runtime.h>
#include <cuda_bf16.h>
#include <cstdint>

#define NNODES 50000
#define NEDGES 800000
#define DIN    256
#define DH     128
#define NLAB   1000
#define NSCANB 196   // ceil(50000/256)

// ---------------- scratch (static device allocations; no cudaMalloc) --------
__device__ float g_ha[NNODES * DH];
__device__ float g_hb[NNODES * DH];
__device__ float g_agg[NNODES * DH];
__device__ float g_res[NNODES * DH];
__device__ int   g_cnt[NNODES];          // zero-init; left zero after each call
__device__ int   g_rowptr[NNODES + 1];
__device__ int   g_cursor[NNODES];
__device__ int   g_bsum[NSCANB];
__device__ int   g_csrc[NEDGES];
__device__ float g_csw[NEDGES];
__device__ float g_cpw[NEDGES];

// ---------------- helpers ----------------------------------------------------
__device__ __forceinline__ uint32_t smem_u32(const void* p) {
    uint32_t a;
    asm("{ .reg .u64 t; cvta.to.shared.u64 t, %1; cvt.u32.u64 %0, t; }" : "=r"(a) : "l"(p));
    return a;
}
__device__ __forceinline__ uint32_t pack_bf2(float e0, float e1) {
    // low half = bf16(e0), high half = bf16(e1)
    uint32_t r;
    asm("cvt.rn.satfinite.bf16x2.f32 %0, %1, %2;" : "=r"(r) : "f"(e1), "f"(e0));
    return r;
}

#define LDSM4(r, addr)                                                          \
    asm volatile("ldmatrix.sync.aligned.m8n8.x4.shared.b16 {%0,%1,%2,%3}, [%4];"\
        : "=r"((r)[0]), "=r"((r)[1]), "=r"((r)[2]), "=r"((r)[3]) : "r"(addr))
#define LDSM4T(r, addr)                                                         \
    asm volatile("ldmatrix.sync.aligned.m8n8.x4.trans.shared.b16 {%0,%1,%2,%3}, [%4];"\
        : "=r"((r)[0]), "=r"((r)[1]), "=r"((r)[2]), "=r"((r)[3]) : "r"(addr))
#define MMA16816(d, a, b)                                                       \
    asm volatile("mma.sync.aligned.m16n8k16.row.col.f32.bf16.bf16.f32 "         \
        "{%0,%1,%2,%3}, {%4,%5,%6,%7}, {%8,%9}, {%0,%1,%2,%3};"                 \
        : "+f"((d)[0]), "+f"((d)[1]), "+f"((d)[2]), "+f"((d)[3])                \
        : "r"((a)[0]), "r"((a)[1]), "r"((a)[2]), "r"((a)[3]),                   \
          "r"((b)[0]), "r"((b)[1]))

// ---------------- CSR build -------------------------------------------------
__global__ void hist_kernel(const int* __restrict__ dst, int E) {
    int i = blockIdx.x * blockDim.x + threadIdx.x;
    if (i < E) atomicAdd(&g_cnt[dst[i]], 1);
}
__global__ void scanA_kernel() {
    __shared__ int wsum[8];
    int i = blockIdx.x * 256 + threadIdx.x;
    int lane = threadIdx.x & 31, wid = threadIdx.x >> 5;
    int v = (i < NNODES) ? g_cnt[i] : 0;
    #pragma unroll
    for (int off = 16; off > 0; off >>= 1) v += __shfl_down_sync(0xFFFFFFFFu, v, off);
    if (lane == 0) wsum[wid] = v;
    __syncthreads();
    if (threadIdx.x == 0) {
        int s = 0;
        #pragma unroll
        for (int w = 0; w < 8; w++) s += wsum[w];
        g_bsum[blockIdx.x] = s;
    }
}
__global__ void scanB_kernel() {
    __shared__ int wsc[8];
    int t = threadIdx.x;
    int lane = t & 31, wid = t >> 5;
    int v = (t < NSCANB) ? g_bsum[t] : 0;
    int incl = v;
    #pragma unroll
    for (int off = 1; off < 32; off <<= 1) {
        int u = __shfl_up_sync(0xFFFFFFFFu, incl, off);
        if (lane >= off) incl += u;
    }
    if (lane == 31) wsc[wid] = incl;
    __syncthreads();
    if (wid == 0) {
        int ws = (lane < 8) ? wsc[lane] : 0;
        #pragma unroll
        for (int off = 1; off < 8; off <<= 1) {
            int u = __shfl_up_sync(0xFFFFFFFFu, ws, off);
            if (lane >= off) ws += u;
        }
        if (lane < 8) wsc[lane] = ws;
    }
    __syncthreads();
    int excl = incl - v + (wid ? wsc[wid - 1] : 0);
    if (t < NSCANB) g_bsum[t] = excl;
    if (t == 255) g_rowptr[NNODES] = excl + v;
}
__global__ void scanC_kernel() {
    __shared__ int wsc[8];
    int i = blockIdx.x * 256 + threadIdx.x;
    int t = threadIdx.x, lane = t & 31, wid = t >> 5;
    int v = (i < NNODES) ? g_cnt[i] : 0;
    int incl = v;
    #pragma unroll
    for (int off = 1; off < 32; off <<= 1) {
        int u = __shfl_up_sync(0xFFFFFFFFu, incl, off);
        if (lane >= off) incl += u;
    }
    if (lane == 31) wsc[wid] = incl;
    __syncthreads();
    if (wid == 0) {
        int ws = (lane < 8) ? wsc[lane] : 0;
        #pragma unroll
        for (int off = 1; off < 8; off <<= 1) {
            int u = __shfl_up_sync(0xFFFFFFFFu, ws, off);
            if (lane >= off) ws += u;
        }
        if (lane < 8) wsc[lane] = ws;
    }
    __syncthreads();
    int excl = incl - v + (wid ? wsc[wid - 1] : 0) + g_bsum[blockIdx.x];
    if (i < NNODES) {
        g_rowptr[i] = excl;
        g_cursor[i] = excl;
        g_cnt[i] = 0;
    }
}
__global__ void scatter_kernel(const int* __restrict__ src, const int* __restrict__ dst,
                               const float* __restrict__ sw, const float* __restrict__ pw,
                               int E) {
    int i = blockIdx.x * blockDim.x + threadIdx.x;
    if (i < E) {
        int d = dst[i];
        int pos = atomicAdd(&g_cursor[d], 1);
        g_csrc[pos] = src[i];
        g_csw[pos]  = sw[i];
        g_cpw[pos]  = pw[i];
    }
}

// ---------------- aggregation: warp per dst node ----------------------------
__global__ void aggregate_kernel(const float* __restrict__ h) {
    int warp = (blockIdx.x * blockDim.x + threadIdx.x) >> 5;
    int lane = threadIdx.x & 31;
    if (warp >= NNODES) return;
    int beg = g_rowptr[warp];
    int end = g_rowptr[warp + 1];
    float4 as = make_float4(0.f, 0.f, 0.f, 0.f);
    float4 ap = make_float4(0.f, 0.f, 0.f, 0.f);
    int e = beg;
    for (; e + 1 < end; e += 2) {
        int   s0 = g_csrc[e], s1 = g_csrc[e + 1];
        float sw0 = g_csw[e], pw0 = g_cpw[e];
        float sw1 = g_csw[e + 1], pw1 = g_cpw[e + 1];
        float4 h0 = *reinterpret_cast<const float4*>(&h[(size_t)s0 * DH + lane * 4]);
        float4 h1 = *reinterpret_cast<const float4*>(&h[(size_t)s1 * DH + lane * 4]);
        as.x += sw0 * h0.x; as.y += sw0 * h0.y; as.z += sw0 * h0.z; as.w += sw0 * h0.w;
        ap.x += pw0 * h0.x; ap.y += pw0 * h0.y; ap.z += pw0 * h0.z; ap.w += pw0 * h0.w;
        as.x += sw1 * h1.x; as.y += sw1 * h1.y; as.z += sw1 * h1.z; as.w += sw1 * h1.w;
        ap.x += pw1 * h1.x; ap.y += pw1 * h1.y; ap.z += pw1 * h1.z; ap.w += pw1 * h1.w;
    }
    if (e < end) {
        int   s0 = g_csrc[e];
        float sw0 = g_csw[e], pw0 = g_cpw[e];
        float4 h0 = *reinterpret_cast<const float4*>(&h[(size_t)s0 * DH + lane * 4]);
        as.x += sw0 * h0.x; as.y += sw0 * h0.y; as.z += sw0 * h0.z; as.w += sw0 * h0.w;
        ap.x += pw0 * h0.x; ap.y += pw0 * h0.y; ap.z += pw0 * h0.z; ap.w += pw0 * h0.w;
    }
    *reinterpret_cast<float4*>(&g_res[(size_t)warp * DH + lane * 4]) = as;
    *reinterpret_cast<float4*>(&g_agg[(size_t)warp * DH + lane * 4]) = ap;
}

// ---------------- bf16-split GEMM on HMMA ------------------------------------
// C[M,Nc] = op(A @ B + bias) [+Res], fp32 in/out.
// fp32 -> (hi,lo) bf16 in-loop; C = AhiBhi + AhiBlo + AloBhi with fp32 accum.
// Block 128x128, BK=32, 16 warps (warp tile 32M x 32N), m16n8k16 HMMA.
// 2-stage smem double buffer + register prefetch; one sync per chunk.
#define SA_STRIDE 80
#define SB_STRIDE 272
#define OFF_A_HI 0
#define OFF_A_LO 10240
#define OFF_B_HI 20480
#define OFF_B_LO 29184
#define BUF_SZ   37888
#define OFF_BIAS 75776
#define SM_TOTAL 76288

template<bool RELU, bool ADDRES>
__global__ __launch_bounds__(512)
void mma_gemm(const float* __restrict__ A, const float* __restrict__ B,
              const float* __restrict__ bias, const float* __restrict__ Res,
              float* __restrict__ C, int M, int K, int Nc) {
    extern __shared__ __align__(16) char smem[];
    const uint32_t sb = smem_u32(smem);
    const int tid  = threadIdx.x;
    const int wid  = tid >> 5;
    const int lane = tid & 31;
    const int rowBase = blockIdx.x * 128;
    const int colBase = blockIdx.y * 128;
    const int wm = (wid >> 2) * 32;   // 0,32,64,96
    const int wn = (wid & 3) * 32;    // 0,32,64,96
    float* bias_s = reinterpret_cast<float*>(smem + OFF_BIAS);

    if (tid < 128) {
        int gc = colBase + tid;
        bias_s[tid] = (gc < Nc) ? bias[gc] : 0.f;
    }

    float4 pa[2], pb[2];

    auto loadA = [&](int k0) {
        #pragma unroll
        for (int u = 0; u < 2; u++) {
            int it = tid + u * 512;          // 1024 items: r=it>>3, kq=(it&7)*4
            int r  = it >> 3;
            int kq = (it & 7) << 2;
            int gr = rowBase + r;
            pa[u] = (gr < M) ? *reinterpret_cast<const float4*>(&A[(size_t)gr * K + k0 + kq])
                             : make_float4(0.f, 0.f, 0.f, 0.f);
        }
    };
    auto loadB = [&](int k0) {
        #pragma unroll
        for (int u = 0; u < 2; u++) {
            int it = tid + u * 512;          // 1024 items: kr=it>>5, nq=(it&31)*4
            int kr = it >> 5;
            int nq = (it & 31) << 2;
            int gc = colBase + nq;
            const float* Brow = &B[(size_t)(k0 + kr) * Nc];
            float4 v;
            if (gc + 3 < Nc) {
                v = *reinterpret_cast<const float4*>(&Brow[gc]);
            } else {
                v.x = (gc     < Nc) ? Brow[gc]     : 0.f;
                v.y = (gc + 1 < Nc) ? Brow[gc + 1] : 0.f;
                v.z = (gc + 2 < Nc) ? Brow[gc + 2] : 0.f;
                v.w = (gc + 3 < Nc) ? Brow[gc + 3] : 0.f;
            }
            pb[u] = v;
        }
    };
    auto storeAB = [&](int buf) {
        const int base = buf * BUF_SZ;
        #pragma unroll
        for (int u = 0; u < 2; u++) {
            int it = tid + u * 512;
            int r  = it >> 3;
            int kq = (it & 7) << 2;
            float4 v = pa[u];
            uint32_t hp01 = pack_bf2(v.x, v.y);
            uint32_t hp23 = pack_bf2(v.z, v.w);
            float hx = __uint_as_float(hp01 << 16);
            float hy = __uint_as_float(hp01 & 0xFFFF0000u);
            float hz = __uint_as_float(hp23 << 16);
            float hw = __uint_as_float(hp23 & 0xFFFF0000u);
            uint32_t lp01 = pack_bf2(v.x - hx, v.y - hy);
            uint32_t lp23 = pack_bf2(v.z - hz, v.w - hw);
            int ad = base + r * SA_STRIDE + kq * 2;
            *reinterpret_cast<uint2*>(smem + OFF_A_HI + ad) = make_uint2(hp01, hp23);
            *reinterpret_cast<uint2*>(smem + OFF_A_LO + ad) = make_uint2(lp01, lp23);
        }
        #pragma unroll
        for (int u = 0; u < 2; u++) {
            int it = tid + u * 512;
            int kr = it >> 5;
            int nq = (it & 31) << 2;
            float4 v = pb[u];
            uint32_t hp01 = pack_bf2(v.x, v.y);
            uint32_t hp23 = pack_bf2(v.z, v.w);
            float hx = __uint_as_float(hp01 << 16);
            float hy = __uint_as_float(hp01 & 0xFFFF0000u);
            float hz = __uint_as_float(hp23 << 16);
            float hw = __uint_as_float(hp23 & 0xFFFF0000u);
            uint32_t lp01 = pack_bf2(v.x - hx, v.y - hy);
            uint32_t lp23 = pack_bf2(v.z - hz, v.w - hw);
            int ad = base + kr * SB_STRIDE + nq * 2;
            *reinterpret_cast<uint2*>(smem + OFF_B_HI + ad) = make_uint2(hp01, hp23);
            *reinterpret_cast<uint2*>(smem + OFF_B_LO + ad) = make_uint2(lp01, lp23);
        }
    };

    float acc[2][4][4];
    #pragma unroll
    for (int mt = 0; mt < 2; mt++)
        #pragma unroll
        for (int nt = 0; nt < 4; nt++)
            #pragma unroll
            for (int q = 0; q < 4; q++) acc[mt][nt][q] = 0.f;

    const int nch = K >> 5;

    // prologue: fill buffer 0, prefetch chunk 1
    loadA(0); loadB(0);
    storeAB(0);
    if (nch > 1) { loadA(32); loadB(32); }
    __syncthreads();

    for (int ch = 0; ch < nch; ch++) {
        const int base = (ch & 1) * BUF_SZ;

        #pragma unroll
        for (int kk = 0; kk < 32; kk += 16) {
            uint32_t ahi[2][4], alo[2][4];
            #pragma unroll
            for (int mt = 0; mt < 2; mt++) {
                int row = wm + mt * 16 + (lane & 15);
                int col = kk + ((lane >> 4) << 3);
                uint32_t aadr = sb + OFF_A_HI + base + row * SA_STRIDE + col * 2;
                LDSM4(ahi[mt], aadr);
                LDSM4(alo[mt], aadr + (OFF_A_LO - OFF_A_HI));
            }
            #pragma unroll
            for (int g = 0; g < 2; g++) {
                int krow = kk + ((lane >> 3) & 1) * 8 + (lane & 7);
                int ncol = wn + g * 16 + ((lane >> 4) << 3);
                uint32_t badr = sb + OFF_B_HI + base + krow * SB_STRIDE + ncol * 2;
                uint32_t bh[4], bl[4];
                LDSM4T(bh, badr);
                LDSM4T(bl, badr + (OFF_B_LO - OFF_B_HI));
                #pragma unroll
                for (int half = 0; half < 2; half++) {
                    int nt = g * 2 + half;
                    #pragma unroll
                    for (int mt = 0; mt < 2; mt++) {
                        MMA16816(acc[mt][nt], ahi[mt], bh + 2 * half);
                        MMA16816(acc[mt][nt], ahi[mt], bl + 2 * half);
                        MMA16816(acc[mt][nt], alo[mt], bh + 2 * half);
                    }
                }
            }
        }

        if (ch + 1 < nch) {
            storeAB((ch + 1) & 1);
            if (ch + 2 < nch) { loadA((ch + 2) << 5); loadB((ch + 2) << 5); }
            __syncthreads();
        }
    }

    // ---- epilogue ----
    const int g4 = lane >> 2;
    const int t4 = lane & 3;
    #pragma unroll
    for (int mt = 0; mt < 2; mt++) {
        #pragma unroll
        for (int half = 0; half < 2; half++) {
            int gr = rowBase + wm + mt * 16 + g4 + half * 8;
            if (gr >= M) continue;
            #pragma unroll
            for (int nt = 0; nt < 4; nt++) {
                int cl = wn + nt * 8 + t4 * 2;
                int gc = colBase + cl;
                float v0 = acc[mt][nt][half * 2]     + bias_s[cl];
                float v1 = acc[mt][nt][half * 2 + 1] + bias_s[cl + 1];
                if (RELU) { v0 = fmaxf(v0, 0.f); v1 = fmaxf(v1, 0.f); }
                if (gc + 1 < Nc) {
                    if (ADDRES) {
                        float2 rr = *reinterpret_cast<const float2*>(&Res[(size_t)gr * Nc + gc]);
                        v0 += rr.x; v1 += rr.y;
                    }
                    *reinterpret_cast<float2*>(&C[(size_t)gr * Nc + gc]) = make_float2(v0, v1);
                } else if (gc < Nc) {
                    if (ADDRES) v0 += Res[(size_t)gr * Nc + gc];
                    C[(size_t)gr * Nc + gc] = v0;
                }
            }
        }
    }
}

// ---------------- launch ----------------------------------------------------
extern "C" void kernel_launch(void* const* d_in, const int* in_sizes, int n_in,
                              void* d_out, int out_size) {
    const float* x      = (const float*)d_in[0];
    const int*   src    = (const int*)  d_in[1];
    const int*   dst    = (const int*)  d_in[2];
    const float* self_w = (const float*)d_in[3];
    const float* ppi_w  = (const float*)d_in[4];
    const float* W_in   = (const float*)d_in[5];
    const float* b_in   = (const float*)d_in[6];
    const float* W1     = (const float*)d_in[7];
    const float* b1     = (const float*)d_in[8];
    const float* W2     = (const float*)d_in[9];
    const float* b2     = (const float*)d_in[10];
    const float* W_out  = (const float*)d_in[11];
    const float* b_out  = (const float*)d_in[12];
    float* out = (float*)d_out;
    const int E = in_sizes[1];

    float *ha, *hb, *agg, *res;
    cudaGetSymbolAddress((void**)&ha,  g_ha);
    cudaGetSymbolAddress((void**)&hb,  g_hb);
    cudaGetSymbolAddress((void**)&agg, g_agg);
    cudaGetSymbolAddress((void**)&res, g_res);

    // one-time host resources (created on the uncaptured correctness call;
    // reused on every call -- streams/events are not device memory)
    static cudaStream_t s2 = nullptr;
    static cudaEvent_t evFork = nullptr, evJoin = nullptr;
    if (s2 == nullptr) {
        cudaStreamCreateWithFlags(&s2, cudaStreamNonBlocking);
        cudaEventCreateWithFlags(&evFork, cudaEventDisableTiming);
        cudaEventCreateWithFlags(&evJoin, cudaEventDisableTiming);
    }

    cudaFuncSetAttribute(mma_gemm<true,  false>, cudaFuncAttributeMaxDynamicSharedMemorySize, SM_TOTAL);
    cudaFuncSetAttribute(mma_gemm<true,  true >, cudaFuncAttributeMaxDynamicSharedMemorySize, SM_TOTAL);
    cudaFuncSetAttribute(mma_gemm<false, false>, cudaFuncAttributeMaxDynamicSharedMemorySize, SM_TOTAL);

    const dim3 blk(512);
    const dim3 g_h((NNODES + 127) / 128, 1);
    const dim3 g_o((NNODES + 127) / 128, (NLAB + 127) / 128);
    const int agg_blocks = (NNODES * 32 + 255) / 256;

    // fork: CSR build chain on s2, input GEMM on main stream (independent)
    cudaEventRecord(evFork, 0);
    cudaStreamWaitEvent(s2, evFork, 0);

    hist_kernel<<<(E + 255) / 256, 256, 0, s2>>>(dst, E);
    scanA_kernel<<<NSCANB, 256, 0, s2>>>();
    scanB_kernel<<<1, 256, 0, s2>>>();
    scanC_kernel<<<NSCANB, 256, 0, s2>>>();
    scatter_kernel<<<(E + 255) / 256, 256, 0, s2>>>(src, dst, self_w, ppi_w, E);
    cudaEventRecord(evJoin, s2);

    // h = relu(x @ W_in + b_in)  (main stream, concurrent with CSR build)
    mma_gemm<true, false><<<g_h, blk, SM_TOTAL>>>(x, W_in, b_in, nullptr, ha, NNODES, DIN, DH);

    // join: aggregate needs both ha and the CSR
    cudaStreamWaitEvent(0, evJoin, 0);

    // layer 1
    aggregate_kernel<<<agg_blocks, 256>>>(ha);
    mma_gemm<true, true><<<g_h, blk, SM_TOTAL>>>(agg, W1, b1, res, hb, NNODES, DH, DH);
    // layer 2
    aggregate_kernel<<<agg_blocks, 256>>>(hb);
    mma_gemm<true, true><<<g_h, blk, SM_TOTAL>>>(agg, W2, b2, res, ha, NNODES, DH, DH);
    // out = h @ W_out + b_out
    mma_gemm<false, false><<<g_o, blk, SM_TOTAL>>>(ha, W_out, b_out, nullptr, out, NNODES, DH, NLAB);
}